// round 15
// baseline (speedup 1.0000x reference)
#include <cuda_runtime.h>
#include <cuda_fp16.h>
#include <cstdint>
#include <cstddef>

#define BATCH 256
#define F0    40
#define KDIM  32
#define NJ    200
#define C0    1600
#define C1    8000
#define M0    8192
#define KG    16
#define M1    512
#define Z0    2      // split-K slices layer 0
#define Z1    32     // split-K slices layer 1

// ---- scratch (static __device__, per harness rules) ----
__device__ __align__(16) __half g_A0[(size_t)M0 * C0];       // [8192, 1600] fp16
__device__ __align__(16) __half g_Xp[(size_t)M1 * C1];       // [512, 8000]  fp16
__device__ __align__(16) __half g_B0[(size_t)256 * C0];      // [256, 1600]
__device__ __align__(16) __half g_B1[(size_t)256 * C1];      // [256, 8000]
__device__ __align__(16) float g_P0[(size_t)Z0 * M0 * NJ];   // gemm0 partials (2 slices)
__device__ __align__(16) float g_P1[(size_t)Z1 * BATCH * NJ];// gemm1 partials

// ================= helpers =================
__device__ __forceinline__ uint32_t smem_u32(const void* p) {
    uint32_t a;
    asm("{ .reg .u64 t; cvta.to.shared.u64 t, %1; cvt.u32.u64 %0, t; }" : "=r"(a) : "l"(p));
    return a;
}

__device__ __forceinline__ float ex2(float x) {
    float y;
    asm("ex2.approx.ftz.f32 %0, %1;" : "=f"(y) : "f"(x));
    return y;
}

__device__ __forceinline__ void ldm_x4(uint32_t* r, uint32_t addr) {
    asm volatile("ldmatrix.sync.aligned.m8n8.x4.shared.b16 {%0,%1,%2,%3}, [%4];"
        : "=r"(r[0]), "=r"(r[1]), "=r"(r[2]), "=r"(r[3]) : "r"(addr));
}

__device__ __forceinline__ void mma_f16(float* d, const uint32_t* a, uint32_t b0, uint32_t b1) {
    asm volatile("mma.sync.aligned.m16n8k16.row.col.f32.f16.f16.f32 "
        "{%0,%1,%2,%3}, {%4,%5,%6,%7}, {%8,%9}, {%0,%1,%2,%3};"
        : "+f"(d[0]), "+f"(d[1]), "+f"(d[2]), "+f"(d[3])
        : "r"(a[0]), "r"(a[1]), "r"(a[2]), "r"(a[3]), "r"(b0), "r"(b1));
}

__device__ __forceinline__ void cp16(uint32_t saddr, const void* gaddr) {
    asm volatile("cp.async.cg.shared.global [%0], [%1], 16;" :: "r"(saddr), "l"(gaddr));
}
__device__ __forceinline__ void cp_commit() { asm volatile("cp.async.commit_group;" ::: "memory"); }
__device__ __forceinline__ void cp_wait1()  { asm volatile("cp.async.wait_group 1;" ::: "memory"); }

// ================= weight prep (both weights, one launch, coalesced) ==========
__global__ void __launch_bounds__(256) bprep2_kernel(
    const float* __restrict__ cw0, const float* __restrict__ cw1,
    __half* __restrict__ B0w, __half* __restrict__ B1w)
{
    __shared__ float t[64][33];
    const int bx = blockIdx.x;
    const float* cw; __half* Bt; int C, cb;
    if (bx < C0 / 64) { cw = cw0; Bt = B0w; C = C0; cb = bx * 64; }
    else              { cw = cw1; Bt = B1w; C = C1; cb = (bx - C0 / 64) * 64; }
    const int jb = blockIdx.y * 32;

    int tx = threadIdx.x & 31, ty = threadIdx.x >> 5;   // j, c-sub
    #pragma unroll
    for (int r = 0; r < 64; r += 8) {
        int c = cb + ty + r;
        int j = jb + tx;
        t[ty + r][tx] = (j < NJ) ? cw[(size_t)c * NJ + j] : 0.f;
    }
    __syncthreads();
    int cx = threadIdx.x & 63, jy = threadIdx.x >> 6;   // c, j-sub
    #pragma unroll
    for (int r = 0; r < 32; r += 4) {
        int j = jb + jy + r;
        Bt[(size_t)j * C + cb + cx] = __float2half(t[cx][jy + r]);
    }
}

// ---------------- Layer 0 producer: column-owned, single barrier ----------------
__global__ void __launch_bounds__(256) prep0_kernel(
    const float* __restrict__ inp, const float* __restrict__ wq,
    const float* __restrict__ wk, const float* __restrict__ wv,
    __half* __restrict__ A0)
{
    __shared__ float u2[KDIM][F0], w[KDIM][F0], v[KDIM][F0];
    const int b = blockIdx.x;
    const int tid = threadIdx.x;

    for (int i = tid; i < KDIM * F0; i += 256) {
        int f = i >> 5, k = i & 31;          // k minor: coalesced
        float x = inp[(size_t)(b * F0 + f) * KDIM + k];
        u2[k][f] = x * wk[f * KDIM + k] * 1.44269504088896f;
        w[k][f]  = x * wv[f * KDIM + k];
        v[k][f]  = x * wq[f * KDIM + k];
    }
    __syncthreads();

    #pragma unroll
    for (int i = 0; i < 5; i++) {
        int idx = tid + 256 * i;             // 0..1279
        int k = idx / 40;
        int g = idx - k * 40;
        float vg = v[k][g];
        float e[F0];
        float s0 = 0.f, s1 = 0.f, s2 = 0.f, s3 = 0.f;
        #pragma unroll
        for (int f = 0; f < F0; f += 4) {
            e[f + 0] = ex2(u2[k][f + 0] * vg);
            e[f + 1] = ex2(u2[k][f + 1] * vg);
            e[f + 2] = ex2(u2[k][f + 2] * vg);
            e[f + 3] = ex2(u2[k][f + 3] * vg);
            s0 += e[f + 0]; s1 += e[f + 1]; s2 += e[f + 2]; s3 += e[f + 3];
        }
        float sinv = 1.0f / ((s0 + s1) + (s2 + s3));
        __half* rowp = A0 + (size_t)(b * KDIM + k) * C0;
        #pragma unroll
        for (int f = 0; f < F0; f++) {
            rowp[f * 40 + g] = __float2half(w[k][f] * e[f] * sinv);
        }
    }
}

// ---------------- Layer 1 producer: f-split thread pairs, shfl softmax sum ----
// grid 1024 = ((b*2)+kg)*2 + gh. Lanes (2j, 2j+1) co-own column g = gh*128 + j;
// lane parity picks f-half (20 fields). Pair combines softmax sums via shfl.
__global__ void __launch_bounds__(256, 3) prep1_kernel(
    const float* __restrict__ inp, const float* __restrict__ P0,
    const float* __restrict__ wq, const float* __restrict__ wk,
    const float* __restrict__ wv, __half* __restrict__ Xp)
{
    __shared__ float u2[KG][F0], w[KG][F0];   // u2 = u * log2(e)
    const int blk = blockIdx.x;       // 1024
    const int gh = blk & 1;
    const int kg = (blk >> 1) & 1;
    const int b = blk >> 2;
    const int tid = threadIdx.x;
    const float* P0b = P0 + (size_t)M0 * NJ;

    for (int i = tid; i < KG * F0; i += 256) {
        int kk = i / F0, f = i - kk * F0;
        int k = kg * KG + kk;
        float x = inp[(size_t)(b * F0 + f) * KDIM + k];
        u2[kk][f] = x * wk[f * KDIM + k] * 1.44269504088896f;
        w[kk][f] = x * wv[f * KDIM + k];
    }
    __syncthreads();

    const int p = tid >> 1;           // pair id 0..127
    const int h = tid & 1;            // f-half
    const int fbase = h * 20;
    const int g = gh * 128 + p;
    const bool act = (g < NJ);
    const int gl = act ? g : (NJ - 1);   // clamp for inactive pairs

    float wqv[KG];
    {
        const float4* wp = reinterpret_cast<const float4*>(wq + gl * KDIM + kg * KG);
        #pragma unroll
        for (int q = 0; q < KG / 4; q++) {
            float4 t = wp[q];
            wqv[q * 4 + 0] = t.x; wqv[q * 4 + 1] = t.y;
            wqv[q * 4 + 2] = t.z; wqv[q * 4 + 3] = t.w;
        }
    }
    float v[KG];
    #pragma unroll
    for (int kk = 0; kk < KG; kk++) {
        size_t idx = (size_t)(b * KDIM + kg * KG + kk) * NJ + gl;
        v[kk] = P0[idx] + P0b[idx];
    }
    #pragma unroll
    for (int kk = 0; kk < KG; kk++) v[kk] *= wqv[kk];

    float acc[20];
    #pragma unroll
    for (int j = 0; j < 20; j++) acc[j] = 0.f;

    for (int kk = 0; kk < KG; kk++) {
        float vk = v[kk];
        float e[20];
        float s0 = 0.f, s1 = 0.f, s2 = 0.f, s3 = 0.f;
        #pragma unroll
        for (int j = 0; j < 20; j += 4) {
            e[j + 0] = ex2(u2[kk][fbase + j + 0] * vk);
            e[j + 1] = ex2(u2[kk][fbase + j + 1] * vk);
            e[j + 2] = ex2(u2[kk][fbase + j + 2] * vk);
            e[j + 3] = ex2(u2[kk][fbase + j + 3] * vk);
            s0 += e[j + 0]; s1 += e[j + 1]; s2 += e[j + 2]; s3 += e[j + 3];
        }
        float s = (s0 + s1) + (s2 + s3);
        s += __shfl_xor_sync(0xFFFFFFFFu, s, 1);   // pair total (all lanes execute)
        float sinv = 1.0f / s;
        #pragma unroll
        for (int j = 0; j < 20; j++)
            acc[j] += w[kk][fbase + j] * e[j] * sinv;
    }

    if (act) {
        __half* rowp = Xp + (size_t)(b * 2 + kg) * C1;
        #pragma unroll
        for (int j = 0; j < 20; j++)
            rowp[(fbase + j) * NJ + g] = __float2half(acc[j]);
    }
}

// ---------------- mma.sync fp16 GEMM body, compile-time NV specialization ----
template<int NV>
__device__ __forceinline__ void gemm_body(
    const __half* __restrict__ A,
    const __half* __restrict__ B,
    float* __restrict__ P, size_t sliceStride,
    int K, int cpz, int nc, int fold, char* sm)
{
    constexpr int n0 = (NV == 128) ? 0 : 128;
    constexpr int brows = (NV >= 128) ? 128 : ((NV + 15) & ~15);   // 128 or 80
    const int tid = threadIdx.x;
    const int lane = tid & 31;
    const int wid = tid >> 5;
    const int wm0 = (wid & 3) * 32;
    const int wn0 = (wid >> 2) * 64;
    const int m0 = blockIdx.x * 128;
    const int lda = K;
    const int c0 = blockIdx.z * cpz;
    int c1 = c0 + cpz; if (c1 > nc) c1 = nc;

    const uint32_t sb = smem_u32(sm);
    float* Pz = P + (size_t)blockIdx.z * sliceStride;

    float acc[2][8][4];
    #pragma unroll
    for (int i = 0; i < 2; i++)
        #pragma unroll
        for (int j = 0; j < 8; j++)
            #pragma unroll
            for (int l = 0; l < 4; l++) acc[i][j][l] = 0.f;

    auto gissue = [&](int c, int st) {
        int col = c * 64;
        uint32_t abase = sb + st * 32768;
        uint32_t bbase = abase + 16384;
        #pragma unroll
        for (int i = 0; i < 4; i++) {
            int idx = tid + 256 * i;
            int row = idx >> 3, q = idx & 7;
            cp16(abase + (row * 8 + (q ^ (row & 7))) * 16,
                 A + (size_t)(m0 + row) * lda + col + q * 8);
        }
        #pragma unroll
        for (int i = 0; i < 4; i++) {
            int idx = tid + 256 * i;
            int row = idx >> 3, q = idx & 7;
            if (row < brows)     // compile-time bound
                cp16(bbase + (row * 8 + (q ^ (row & 7))) * 16,
                     B + (size_t)(n0 + row) * lda + col + q * 8);
        }
        cp_commit();
    };

    if (c0 < c1) gissue(c0, 0); else cp_commit();
    if (c0 + 1 < c1) gissue(c0 + 1, 1); else cp_commit();

    const int t3 = lane >> 3;
    const int r8 = lane & 7;
    const bool fullwarp = (NV >= 128) || (wn0 == 0);

    for (int c = c0; c < c1; c++) {
        int rel = c - c0;
        int st = rel % 3;
        cp_wait1();
        __syncthreads();
        if (c + 2 < c1) gissue(c + 2, (rel + 2) % 3);
        uint32_t ab = sb + st * 32768;
        uint32_t bb = ab + 16384;
        #pragma unroll
        for (int ks = 0; ks < 4; ks++) {
            int kc = ks * 2;
            uint32_t afr[2][4], bfr[4][4];
            #pragma unroll
            for (int mt = 0; mt < 2; mt++) {
                int m = wm0 + mt * 16 + (t3 & 1) * 8 + r8;
                int q = kc + (t3 >> 1);
                ldm_x4(afr[mt], ab + (m * 8 + (q ^ (m & 7))) * 16);
            }
            if (fullwarp) {
                #pragma unroll
                for (int np = 0; np < 4; np++) {
                    int n = wn0 + np * 16 + (t3 >> 1) * 8 + r8;
                    int q = kc + (t3 & 1);
                    ldm_x4(bfr[np], bb + (n * 8 + (q ^ (n & 7))) * 16);
                }
                #pragma unroll
                for (int mt = 0; mt < 2; mt++)
                    #pragma unroll
                    for (int nt = 0; nt < 8; nt++)
                        mma_f16(acc[mt][nt], afr[mt],
                                bfr[nt >> 1][(nt & 1) * 2], bfr[nt >> 1][(nt & 1) * 2 + 1]);
            } else {
                int n = wn0 + (t3 >> 1) * 8 + r8;
                int q = kc + (t3 & 1);
                ldm_x4(bfr[0], bb + (n * 8 + (q ^ (n & 7))) * 16);
                #pragma unroll
                for (int mt = 0; mt < 2; mt++)
                    mma_f16(acc[mt][0], afr[mt], bfr[0][0], bfr[0][1]);
            }
        }
    }

    // epilogue: plain vectorized stores into this z-slice
    const int g = lane >> 2, t = lane & 3;
    if (!fold) {
        #pragma unroll
        for (int mt = 0; mt < 2; mt++) {
            #pragma unroll
            for (int nt = 0; nt < 8; nt++) {
                int row = m0 + wm0 + mt * 16 + g;
                int col = n0 + wn0 + nt * 8 + t * 2;
                if (col < NJ) {
                    *reinterpret_cast<float2*>(&Pz[(size_t)row * NJ + col]) =
                        make_float2(acc[mt][nt][0], acc[mt][nt][1]);
                    *reinterpret_cast<float2*>(&Pz[(size_t)(row + 8) * NJ + col]) =
                        make_float2(acc[mt][nt][2], acc[mt][nt][3]);
                }
            }
        }
    } else {
        #pragma unroll
        for (int mt = 0; mt < 2; mt++) {
            #pragma unroll
            for (int nt = 0; nt < 8; nt++) {
                float v0 = acc[mt][nt][0] + __shfl_xor_sync(0xFFFFFFFFu, acc[mt][nt][0], 4);
                float v1 = acc[mt][nt][1] + __shfl_xor_sync(0xFFFFFFFFu, acc[mt][nt][1], 4);
                float v2 = acc[mt][nt][2] + __shfl_xor_sync(0xFFFFFFFFu, acc[mt][nt][2], 4);
                float v3 = acc[mt][nt][3] + __shfl_xor_sync(0xFFFFFFFFu, acc[mt][nt][3], 4);
                int row = m0 + wm0 + mt * 16 + g;
                int col = n0 + wn0 + nt * 8 + t * 2;
                if ((g & 1) == 0 && col < NJ) {
                    int or0 = row >> 1;
                    int or1 = (row + 8) >> 1;
                    *reinterpret_cast<float2*>(&Pz[(size_t)or0 * NJ + col]) = make_float2(v0, v1);
                    *reinterpret_cast<float2*>(&Pz[(size_t)or1 * NJ + col]) = make_float2(v2, v3);
                }
            }
        }
    }
}

__global__ void __launch_bounds__(256, 2) mma_gemm_kernel(
    const __half* __restrict__ A,
    const __half* __restrict__ B,
    float* __restrict__ P, size_t sliceStride,
    int K, int cpz, int nc, int fold)
{
    extern __shared__ char sm[];       // 3 stages x (A 16KB + B 16KB) = 96KB
    if (blockIdx.y == 0)
        gemm_body<128>(A, B, P, sliceStride, K, cpz, nc, fold, sm);
    else
        gemm_body<72>(A, B, P, sliceStride, K, cpz, nc, fold, sm);
}

// ---------------- Final reduce: [B, 400], sums gemm0 slices inline ----------
__global__ void reduce_kernel(const float* __restrict__ P0,
                              const float* __restrict__ P1,
                              float* __restrict__ res)
{
    int i = blockIdx.x * 256 + threadIdx.x;
    if (i >= BATCH * 2 * NJ) return;
    int b = i / (2 * NJ), j = i % (2 * NJ);
    if (j < NJ) {
        const float* P0b = P0 + (size_t)M0 * NJ;
        float s = 0.f;
        #pragma unroll
        for (int k = 0; k < KDIM; k++) {
            size_t idx = (size_t)(b * KDIM + k) * NJ + j;
            s += P0[idx] + P0b[idx];
        }
        res[i] = s;
    } else {
        float s = 0.f;
        #pragma unroll
        for (int z = 0; z < Z1; z++)
            s += P1[(size_t)z * BATCH * NJ + (size_t)b * NJ + (j - NJ)];
        res[i] = s;
    }
}

extern "C" void kernel_launch(void* const* d_in, const int* in_sizes, int n_in,
                              void* d_out, int out_size)
{
    const float* inp = (const float*)d_in[0];
    const float* wq0 = (const float*)d_in[1];
    const float* wk0 = (const float*)d_in[2];
    const float* wv0 = (const float*)d_in[3];
    const float* cw0 = (const float*)d_in[4];
    const float* wq1 = (const float*)d_in[5];
    const float* wk1 = (const float*)d_in[6];
    const float* wv1 = (const float*)d_in[7];
    const float* cw1 = (const float*)d_in[8];
    float* out = (float*)d_out;

    __half *A0, *Xp, *B0, *B1;
    float *P0, *P1;
    cudaGetSymbolAddress((void**)&A0, g_A0);
    cudaGetSymbolAddress((void**)&Xp, g_Xp);
    cudaGetSymbolAddress((void**)&B0, g_B0);
    cudaGetSymbolAddress((void**)&B1, g_B1);
    cudaGetSymbolAddress((void**)&P0, g_P0);
    cudaGetSymbolAddress((void**)&P1, g_P1);

    cudaFuncSetAttribute(mma_gemm_kernel, cudaFuncAttributeMaxDynamicSharedMemorySize, 98304);

    // both weight transposes + fp16 casts in ONE launch
    bprep2_kernel<<<dim3(C0 / 64 + C1 / 64, 8), 256>>>(cw0, cw1, B0, B1);

    // layer 0
    prep0_kernel<<<BATCH, 256>>>(inp, wq0, wk0, wv0, A0);
    // M=8192 (64 tiles), 2 n-tiles, nc=25 chunks (fp16), Z0=2 (cpz=13) -> 256 CTAs, 1 wave
    mma_gemm_kernel<<<dim3(64, 2, Z0), 256, 98304>>>(A0, B0, P0, (size_t)M0 * NJ, C0, 13, 25, 0);

    // layer 1 (f-split pair producer; sums P0 slices inline)
    prep1_kernel<<<BATCH * 4, 256>>>(inp, P0, wq1, wk1, wv1, Xp);
    // M=512 (4 tiles), nc=125 chunks (fp16), Z1=32 (cpz=4) -> 256 CTAs (1 wave)
    mma_gemm_kernel<<<dim3(4, 2, Z1), 256, 98304>>>(Xp, B1, P1, (size_t)BATCH * NJ, C1, 4, 125, 1);

    reduce_kernel<<<(BATCH * 2 * NJ + 255) / 256, 256>>>(P0, P1, out);
}

// round 16
// speedup vs baseline: 1.0224x; 1.0224x over previous
#include <cuda_runtime.h>
#include <cuda_fp16.h>
#include <cstdint>
#include <cstddef>

#define BATCH 256
#define F0    40
#define KDIM  32
#define NJ    200
#define C0    1600
#define C1    8000
#define M0    8192
#define KG    16
#define M1    512
#define Z0    2      // split-K slices layer 0
#define Z1    32     // split-K slices layer 1

// ---- scratch (static __device__, per harness rules) ----
__device__ __align__(16) __half g_A0[(size_t)M0 * C0];       // [8192, 1600] fp16
__device__ __align__(16) __half g_Xp[(size_t)M1 * C1];       // [512, 8000]  fp16
__device__ __align__(16) __half g_B0[(size_t)256 * C0];      // [256, 1600]
__device__ __align__(16) __half g_B1[(size_t)256 * C1];      // [256, 8000]
__device__ __align__(16) float g_P0[(size_t)Z0 * M0 * NJ];   // gemm0 partials (2 slices)
__device__ __align__(16) float g_P1[(size_t)Z1 * BATCH * NJ];// gemm1 partials

// ================= helpers =================
__device__ __forceinline__ uint32_t smem_u32(const void* p) {
    uint32_t a;
    asm("{ .reg .u64 t; cvta.to.shared.u64 t, %1; cvt.u32.u64 %0, t; }" : "=r"(a) : "l"(p));
    return a;
}

__device__ __forceinline__ float ex2(float x) {
    float y;
    asm("ex2.approx.ftz.f32 %0, %1;" : "=f"(y) : "f"(x));
    return y;
}

__device__ __forceinline__ void ldm_x4(uint32_t* r, uint32_t addr) {
    asm volatile("ldmatrix.sync.aligned.m8n8.x4.shared.b16 {%0,%1,%2,%3}, [%4];"
        : "=r"(r[0]), "=r"(r[1]), "=r"(r[2]), "=r"(r[3]) : "r"(addr));
}

__device__ __forceinline__ void mma_f16(float* d, const uint32_t* a, uint32_t b0, uint32_t b1) {
    asm volatile("mma.sync.aligned.m16n8k16.row.col.f32.f16.f16.f32 "
        "{%0,%1,%2,%3}, {%4,%5,%6,%7}, {%8,%9}, {%0,%1,%2,%3};"
        : "+f"(d[0]), "+f"(d[1]), "+f"(d[2]), "+f"(d[3])
        : "r"(a[0]), "r"(a[1]), "r"(a[2]), "r"(a[3]), "r"(b0), "r"(b1));
}

__device__ __forceinline__ void cp16(uint32_t saddr, const void* gaddr) {
    asm volatile("cp.async.cg.shared.global [%0], [%1], 16;" :: "r"(saddr), "l"(gaddr));
}
__device__ __forceinline__ void cp_commit() { asm volatile("cp.async.commit_group;" ::: "memory"); }
__device__ __forceinline__ void cp_wait1()  { asm volatile("cp.async.wait_group 1;" ::: "memory"); }

// ================= weight prep (both weights, one launch, coalesced) ==========
__global__ void __launch_bounds__(256) bprep2_kernel(
    const float* __restrict__ cw0, const float* __restrict__ cw1,
    __half* __restrict__ B0w, __half* __restrict__ B1w)
{
    __shared__ float t[64][33];
    const int bx = blockIdx.x;
    const float* cw; __half* Bt; int C, cb;
    if (bx < C0 / 64) { cw = cw0; Bt = B0w; C = C0; cb = bx * 64; }
    else              { cw = cw1; Bt = B1w; C = C1; cb = (bx - C0 / 64) * 64; }
    const int jb = blockIdx.y * 32;

    int tx = threadIdx.x & 31, ty = threadIdx.x >> 5;   // j, c-sub
    #pragma unroll
    for (int r = 0; r < 64; r += 8) {
        int c = cb + ty + r;
        int j = jb + tx;
        t[ty + r][tx] = (j < NJ) ? cw[(size_t)c * NJ + j] : 0.f;
    }
    __syncthreads();
    int cx = threadIdx.x & 63, jy = threadIdx.x >> 6;   // c, j-sub
    #pragma unroll
    for (int r = 0; r < 32; r += 4) {
        int j = jb + jy + r;
        Bt[(size_t)j * C + cb + cx] = __float2half(t[cx][jy + r]);
    }
}

// ---------------- Layer 0 producer: column-owned, single barrier ----------------
__global__ void __launch_bounds__(256) prep0_kernel(
    const float* __restrict__ inp, const float* __restrict__ wq,
    const float* __restrict__ wk, const float* __restrict__ wv,
    __half* __restrict__ A0)
{
    __shared__ float u2[KDIM][F0], w[KDIM][F0], v[KDIM][F0];
    const int b = blockIdx.x;
    const int tid = threadIdx.x;

    for (int i = tid; i < KDIM * F0; i += 256) {
        int f = i >> 5, k = i & 31;          // k minor: coalesced
        float x = inp[(size_t)(b * F0 + f) * KDIM + k];
        u2[k][f] = x * wk[f * KDIM + k] * 1.44269504088896f;
        w[k][f]  = x * wv[f * KDIM + k];
        v[k][f]  = x * wq[f * KDIM + k];
    }
    __syncthreads();

    #pragma unroll
    for (int i = 0; i < 5; i++) {
        int idx = tid + 256 * i;             // 0..1279
        int k = idx / 40;
        int g = idx - k * 40;
        float vg = v[k][g];
        float e[F0];
        float s0 = 0.f, s1 = 0.f, s2 = 0.f, s3 = 0.f;
        #pragma unroll
        for (int f = 0; f < F0; f += 4) {
            e[f + 0] = ex2(u2[k][f + 0] * vg);
            e[f + 1] = ex2(u2[k][f + 1] * vg);
            e[f + 2] = ex2(u2[k][f + 2] * vg);
            e[f + 3] = ex2(u2[k][f + 3] * vg);
            s0 += e[f + 0]; s1 += e[f + 1]; s2 += e[f + 2]; s3 += e[f + 3];
        }
        float sinv = 1.0f / ((s0 + s1) + (s2 + s3));
        __half* rowp = A0 + (size_t)(b * KDIM + k) * C0;
        #pragma unroll
        for (int f = 0; f < F0; f++) {
            rowp[f * 40 + g] = __float2half(w[k][f] * e[f] * sinv);
        }
    }
}

// ---------------- Layer 1 producer: column-owned, fused w-multiply pass -------
// block = (b, kg) : 512 blocks x 256 threads. Thread g (< 200) owns column g.
// smem holds (u*log2e, w) pairs; pass 1 computes tw = w*e and the softmax sum,
// pass 2 is a register-only FFMA with sinv.
__global__ void __launch_bounds__(256) prep1_kernel(
    const float* __restrict__ inp, const float* __restrict__ P0,
    const float* __restrict__ wq, const float* __restrict__ wk,
    const float* __restrict__ wv, __half* __restrict__ Xp)
{
    __shared__ float2 uw[KG][F0];     // (u*log2e, w)
    const int blk = blockIdx.x;       // 512 = b*2 + kg
    const int kg = blk & 1;
    const int b = blk >> 1;
    const int tid = threadIdx.x;
    const float* P0b = P0 + (size_t)M0 * NJ;

    for (int i = tid; i < KG * F0; i += 256) {
        int kk = i / F0, f = i - kk * F0;
        int k = kg * KG + kk;
        float x = inp[(size_t)(b * F0 + f) * KDIM + k];
        uw[kk][f] = make_float2(x * wk[f * KDIM + k] * 1.44269504088896f,
                                x * wv[f * KDIM + k]);
    }
    __syncthreads();

    if (tid >= NJ) return;            // no further barriers: safe
    const int g = tid;

    float wqv[KG];
    {
        const float4* wp = reinterpret_cast<const float4*>(wq + g * KDIM + kg * KG);
        #pragma unroll
        for (int q = 0; q < KG / 4; q++) {
            float4 t = wp[q];
            wqv[q * 4 + 0] = t.x; wqv[q * 4 + 1] = t.y;
            wqv[q * 4 + 2] = t.z; wqv[q * 4 + 3] = t.w;
        }
    }
    float v[KG];
    #pragma unroll
    for (int kk = 0; kk < KG; kk++) {
        size_t idx = (size_t)(b * KDIM + kg * KG + kk) * NJ + g;
        v[kk] = P0[idx] + P0b[idx];
    }
    #pragma unroll
    for (int kk = 0; kk < KG; kk++) v[kk] *= wqv[kk];

    float acc[F0];
    #pragma unroll
    for (int f = 0; f < F0; f++) acc[f] = 0.f;

    for (int kk = 0; kk < KG; kk++) {
        float vk = v[kk];
        float tw[F0];                  // w * e
        float s0 = 0.f, s1 = 0.f, s2 = 0.f, s3 = 0.f;
        #pragma unroll
        for (int f = 0; f < F0; f += 4) {
            float2 p0 = uw[kk][f + 0];
            float2 p1 = uw[kk][f + 1];
            float2 p2 = uw[kk][f + 2];
            float2 p3 = uw[kk][f + 3];
            float e0 = ex2(p0.x * vk);
            float e1 = ex2(p1.x * vk);
            float e2 = ex2(p2.x * vk);
            float e3 = ex2(p3.x * vk);
            s0 += e0; s1 += e1; s2 += e2; s3 += e3;
            tw[f + 0] = p0.y * e0;
            tw[f + 1] = p1.y * e1;
            tw[f + 2] = p2.y * e2;
            tw[f + 3] = p3.y * e3;
        }
        float sinv = 1.0f / ((s0 + s1) + (s2 + s3));
        #pragma unroll
        for (int f = 0; f < F0; f++)
            acc[f] = fmaf(tw[f], sinv, acc[f]);
    }

    __half* rowp = Xp + (size_t)blk * C1;
    #pragma unroll
    for (int f = 0; f < F0; f++) {
        rowp[f * NJ + g] = __float2half(acc[f]);
    }
}

// ---------------- mma.sync fp16 GEMM body, compile-time NV specialization ----
template<int NV>
__device__ __forceinline__ void gemm_body(
    const __half* __restrict__ A,
    const __half* __restrict__ B,
    float* __restrict__ P, size_t sliceStride,
    int K, int cpz, int nc, int fold, char* sm)
{
    constexpr int n0 = (NV == 128) ? 0 : 128;
    constexpr int brows = (NV >= 128) ? 128 : ((NV + 15) & ~15);   // 128 or 80
    const int tid = threadIdx.x;
    const int lane = tid & 31;
    const int wid = tid >> 5;
    const int wm0 = (wid & 3) * 32;
    const int wn0 = (wid >> 2) * 64;
    const int m0 = blockIdx.x * 128;
    const int lda = K;
    const int c0 = blockIdx.z * cpz;
    int c1 = c0 + cpz; if (c1 > nc) c1 = nc;

    const uint32_t sb = smem_u32(sm);
    float* Pz = P + (size_t)blockIdx.z * sliceStride;

    float acc[2][8][4];
    #pragma unroll
    for (int i = 0; i < 2; i++)
        #pragma unroll
        for (int j = 0; j < 8; j++)
            #pragma unroll
            for (int l = 0; l < 4; l++) acc[i][j][l] = 0.f;

    auto gissue = [&](int c, int st) {
        int col = c * 64;
        uint32_t abase = sb + st * 32768;
        uint32_t bbase = abase + 16384;
        #pragma unroll
        for (int i = 0; i < 4; i++) {
            int idx = tid + 256 * i;
            int row = idx >> 3, q = idx & 7;
            cp16(abase + (row * 8 + (q ^ (row & 7))) * 16,
                 A + (size_t)(m0 + row) * lda + col + q * 8);
        }
        #pragma unroll
        for (int i = 0; i < 4; i++) {
            int idx = tid + 256 * i;
            int row = idx >> 3, q = idx & 7;
            if (row < brows)     // compile-time bound
                cp16(bbase + (row * 8 + (q ^ (row & 7))) * 16,
                     B + (size_t)(n0 + row) * lda + col + q * 8);
        }
        cp_commit();
    };

    if (c0 < c1) gissue(c0, 0); else cp_commit();
    if (c0 + 1 < c1) gissue(c0 + 1, 1); else cp_commit();

    const int t3 = lane >> 3;
    const int r8 = lane & 7;
    const bool fullwarp = (NV >= 128) || (wn0 == 0);

    for (int c = c0; c < c1; c++) {
        int rel = c - c0;
        int st = rel % 3;
        cp_wait1();
        __syncthreads();
        if (c + 2 < c1) gissue(c + 2, (rel + 2) % 3);
        uint32_t ab = sb + st * 32768;
        uint32_t bb = ab + 16384;
        #pragma unroll
        for (int ks = 0; ks < 4; ks++) {
            int kc = ks * 2;
            uint32_t afr[2][4], bfr[4][4];
            #pragma unroll
            for (int mt = 0; mt < 2; mt++) {
                int m = wm0 + mt * 16 + (t3 & 1) * 8 + r8;
                int q = kc + (t3 >> 1);
                ldm_x4(afr[mt], ab + (m * 8 + (q ^ (m & 7))) * 16);
            }
            if (fullwarp) {
                #pragma unroll
                for (int np = 0; np < 4; np++) {
                    int n = wn0 + np * 16 + (t3 >> 1) * 8 + r8;
                    int q = kc + (t3 & 1);
                    ldm_x4(bfr[np], bb + (n * 8 + (q ^ (n & 7))) * 16);
                }
                #pragma unroll
                for (int mt = 0; mt < 2; mt++)
                    #pragma unroll
                    for (int nt = 0; nt < 8; nt++)
                        mma_f16(acc[mt][nt], afr[mt],
                                bfr[nt >> 1][(nt & 1) * 2], bfr[nt >> 1][(nt & 1) * 2 + 1]);
            } else {
                int n = wn0 + (t3 >> 1) * 8 + r8;
                int q = kc + (t3 & 1);
                ldm_x4(bfr[0], bb + (n * 8 + (q ^ (n & 7))) * 16);
                #pragma unroll
                for (int mt = 0; mt < 2; mt++)
                    mma_f16(acc[mt][0], afr[mt], bfr[0][0], bfr[0][1]);
            }
        }
    }

    // epilogue: plain vectorized stores into this z-slice
    const int g = lane >> 2, t = lane & 3;
    if (!fold) {
        #pragma unroll
        for (int mt = 0; mt < 2; mt++) {
            #pragma unroll
            for (int nt = 0; nt < 8; nt++) {
                int row = m0 + wm0 + mt * 16 + g;
                int col = n0 + wn0 + nt * 8 + t * 2;
                if (col < NJ) {
                    *reinterpret_cast<float2*>(&Pz[(size_t)row * NJ + col]) =
                        make_float2(acc[mt][nt][0], acc[mt][nt][1]);
                    *reinterpret_cast<float2*>(&Pz[(size_t)(row + 8) * NJ + col]) =
                        make_float2(acc[mt][nt][2], acc[mt][nt][3]);
                }
            }
        }
    } else {
        #pragma unroll
        for (int mt = 0; mt < 2; mt++) {
            #pragma unroll
            for (int nt = 0; nt < 8; nt++) {
                float v0 = acc[mt][nt][0] + __shfl_xor_sync(0xFFFFFFFFu, acc[mt][nt][0], 4);
                float v1 = acc[mt][nt][1] + __shfl_xor_sync(0xFFFFFFFFu, acc[mt][nt][1], 4);
                float v2 = acc[mt][nt][2] + __shfl_xor_sync(0xFFFFFFFFu, acc[mt][nt][2], 4);
                float v3 = acc[mt][nt][3] + __shfl_xor_sync(0xFFFFFFFFu, acc[mt][nt][3], 4);
                int row = m0 + wm0 + mt * 16 + g;
                int col = n0 + wn0 + nt * 8 + t * 2;
                if ((g & 1) == 0 && col < NJ) {
                    int or0 = row >> 1;
                    int or1 = (row + 8) >> 1;
                    *reinterpret_cast<float2*>(&Pz[(size_t)or0 * NJ + col]) = make_float2(v0, v1);
                    *reinterpret_cast<float2*>(&Pz[(size_t)or1 * NJ + col]) = make_float2(v2, v3);
                }
            }
        }
    }
}

__global__ void __launch_bounds__(256, 2) mma_gemm_kernel(
    const __half* __restrict__ A,
    const __half* __restrict__ B,
    float* __restrict__ P, size_t sliceStride,
    int K, int cpz, int nc, int fold)
{
    extern __shared__ char sm[];       // 3 stages x (A 16KB + B 16KB) = 96KB
    if (blockIdx.y == 0)
        gemm_body<128>(A, B, P, sliceStride, K, cpz, nc, fold, sm);
    else
        gemm_body<72>(A, B, P, sliceStride, K, cpz, nc, fold, sm);
}

// ---------------- Final reduce: [B, 400], sums gemm0 slices inline ----------
__global__ void reduce_kernel(const float* __restrict__ P0,
                              const float* __restrict__ P1,
                              float* __restrict__ res)
{
    int i = blockIdx.x * 256 + threadIdx.x;
    if (i >= BATCH * 2 * NJ) return;
    int b = i / (2 * NJ), j = i % (2 * NJ);
    if (j < NJ) {
        const float* P0b = P0 + (size_t)M0 * NJ;
        float s = 0.f;
        #pragma unroll
        for (int k = 0; k < KDIM; k++) {
            size_t idx = (size_t)(b * KDIM + k) * NJ + j;
            s += P0[idx] + P0b[idx];
        }
        res[i] = s;
    } else {
        float s = 0.f;
        #pragma unroll
        for (int z = 0; z < Z1; z++)
            s += P1[(size_t)z * BATCH * NJ + (size_t)b * NJ + (j - NJ)];
        res[i] = s;
    }
}

extern "C" void kernel_launch(void* const* d_in, const int* in_sizes, int n_in,
                              void* d_out, int out_size)
{
    const float* inp = (const float*)d_in[0];
    const float* wq0 = (const float*)d_in[1];
    const float* wk0 = (const float*)d_in[2];
    const float* wv0 = (const float*)d_in[3];
    const float* cw0 = (const float*)d_in[4];
    const float* wq1 = (const float*)d_in[5];
    const float* wk1 = (const float*)d_in[6];
    const float* wv1 = (const float*)d_in[7];
    const float* cw1 = (const float*)d_in[8];
    float* out = (float*)d_out;

    __half *A0, *Xp, *B0, *B1;
    float *P0, *P1;
    cudaGetSymbolAddress((void**)&A0, g_A0);
    cudaGetSymbolAddress((void**)&Xp, g_Xp);
    cudaGetSymbolAddress((void**)&B0, g_B0);
    cudaGetSymbolAddress((void**)&B1, g_B1);
    cudaGetSymbolAddress((void**)&P0, g_P0);
    cudaGetSymbolAddress((void**)&P1, g_P1);

    cudaFuncSetAttribute(mma_gemm_kernel, cudaFuncAttributeMaxDynamicSharedMemorySize, 98304);

    // both weight transposes + fp16 casts in ONE launch
    bprep2_kernel<<<dim3(C0 / 64 + C1 / 64, 8), 256>>>(cw0, cw1, B0, B1);

    // layer 0
    prep0_kernel<<<BATCH, 256>>>(inp, wq0, wk0, wv0, A0);
    // M=8192 (64 tiles), 2 n-tiles, nc=25 chunks (fp16), Z0=2 (cpz=13) -> 256 CTAs, 1 wave
    mma_gemm_kernel<<<dim3(64, 2, Z0), 256, 98304>>>(A0, B0, P0, (size_t)M0 * NJ, C0, 13, 25, 0);

    // layer 1 (column-owned producer, fused w-multiply; sums P0 slices inline)
    prep1_kernel<<<M1, 256>>>(inp, P0, wq1, wk1, wv1, Xp);
    // M=512 (4 tiles), nc=125 chunks (fp16), Z1=32 (cpz=4) -> 256 CTAs (1 wave)
    mma_gemm_kernel<<<dim3(4, 2, Z1), 256, 98304>>>(Xp, B1, P1, (size_t)BATCH * NJ, C1, 4, 125, 1);

    reduce_kernel<<<(BATCH * 2 * NJ + 255) / 256, 256>>>(P0, P1, out);
}

// round 17
// speedup vs baseline: 1.1116x; 1.0872x over previous
#include <cuda_runtime.h>
#include <cuda_fp16.h>
#include <cstdint>
#include <cstddef>

#define BATCH 256
#define F0    40
#define KDIM  32
#define NJ    200
#define C0    1600
#define C1    8000
#define M0    8192
#define KG    16
#define M1    256
#define Z0    2      // split-K slices layer 0
#define Z1    25     // split-K slices layer 1 (25*5 = 125 chunks exact)

// ---- scratch (static __device__, per harness rules) ----
__device__ __align__(16) __half g_A0[(size_t)M0 * C0];       // [8192, 1600] fp16
__device__ __align__(16) __half g_Xp[(size_t)M1 * C1];       // [256, 8000]  fp16
__device__ __align__(16) __half g_B0[(size_t)256 * C0];      // [256, 1600]
__device__ __align__(16) __half g_B1[(size_t)256 * C1];      // [256, 8000]
__device__ __align__(16) float g_P0[(size_t)Z0 * M0 * NJ];   // gemm0 partials (2 slices)
__device__ __align__(16) float g_P1[(size_t)Z1 * BATCH * NJ];// gemm1 partials

// ================= helpers =================
__device__ __forceinline__ uint32_t smem_u32(const void* p) {
    uint32_t a;
    asm("{ .reg .u64 t; cvta.to.shared.u64 t, %1; cvt.u32.u64 %0, t; }" : "=r"(a) : "l"(p));
    return a;
}

__device__ __forceinline__ float ex2(float x) {
    float y;
    asm("ex2.approx.ftz.f32 %0, %1;" : "=f"(y) : "f"(x));
    return y;
}

__device__ __forceinline__ void ldm_x4(uint32_t* r, uint32_t addr) {
    asm volatile("ldmatrix.sync.aligned.m8n8.x4.shared.b16 {%0,%1,%2,%3}, [%4];"
        : "=r"(r[0]), "=r"(r[1]), "=r"(r[2]), "=r"(r[3]) : "r"(addr));
}

__device__ __forceinline__ void mma_f16(float* d, const uint32_t* a, uint32_t b0, uint32_t b1) {
    asm volatile("mma.sync.aligned.m16n8k16.row.col.f32.f16.f16.f32 "
        "{%0,%1,%2,%3}, {%4,%5,%6,%7}, {%8,%9}, {%0,%1,%2,%3};"
        : "+f"(d[0]), "+f"(d[1]), "+f"(d[2]), "+f"(d[3])
        : "r"(a[0]), "r"(a[1]), "r"(a[2]), "r"(a[3]), "r"(b0), "r"(b1));
}

__device__ __forceinline__ void cp16(uint32_t saddr, const void* gaddr) {
    asm volatile("cp.async.cg.shared.global [%0], [%1], 16;" :: "r"(saddr), "l"(gaddr));
}
__device__ __forceinline__ void cp_commit() { asm volatile("cp.async.commit_group;" ::: "memory"); }
__device__ __forceinline__ void cp_wait1()  { asm volatile("cp.async.wait_group 1;" ::: "memory"); }

// ======== merged producer: prep0 (blocks 0..255) + weight prep (rest) ========
__global__ void __launch_bounds__(256) prep0b_kernel(
    const float* __restrict__ inp, const float* __restrict__ wq,
    const float* __restrict__ wk, const float* __restrict__ wv,
    __half* __restrict__ A0,
    const float* __restrict__ cw0, const float* __restrict__ cw1,
    __half* __restrict__ B0w, __half* __restrict__ B1w)
{
    __shared__ float sm0[3][KDIM][F0];     // prep0: u2/w/v ; bprep reuses as t[64][33]
    const int tid = threadIdx.x;

    if (blockIdx.x < BATCH) {
        // ---------------- prep0 role ----------------
        float (*u2)[F0] = sm0[0];
        float (*w)[F0]  = sm0[1];
        float (*v)[F0]  = sm0[2];
        const int b = blockIdx.x;

        for (int i = tid; i < KDIM * F0; i += 256) {
            int f = i >> 5, k = i & 31;      // k minor: coalesced
            float x = inp[(size_t)(b * F0 + f) * KDIM + k];
            u2[k][f] = x * wk[f * KDIM + k] * 1.44269504088896f;
            w[k][f]  = x * wv[f * KDIM + k];
            v[k][f]  = x * wq[f * KDIM + k];
        }
        __syncthreads();

        #pragma unroll
        for (int i = 0; i < 5; i++) {
            int idx = tid + 256 * i;         // 0..1279
            int k = idx / 40;
            int g = idx - k * 40;
            float vg = v[k][g];
            float e[F0];
            float s0 = 0.f, s1 = 0.f, s2 = 0.f, s3 = 0.f;
            #pragma unroll
            for (int f = 0; f < F0; f += 4) {
                e[f + 0] = ex2(u2[k][f + 0] * vg);
                e[f + 1] = ex2(u2[k][f + 1] * vg);
                e[f + 2] = ex2(u2[k][f + 2] * vg);
                e[f + 3] = ex2(u2[k][f + 3] * vg);
                s0 += e[f + 0]; s1 += e[f + 1]; s2 += e[f + 2]; s3 += e[f + 3];
            }
            float sinv = 1.0f / ((s0 + s1) + (s2 + s3));
            __half* rowp = A0 + (size_t)(b * KDIM + k) * C0;
            #pragma unroll
            for (int f = 0; f < F0; f++) {
                rowp[f * 40 + g] = __float2half(w[k][f] * e[f] * sinv);
            }
        }
    } else {
        // ---------------- bprep role ----------------
        float (*t)[33] = reinterpret_cast<float(*)[33]>(&sm0[0][0][0]);  // 64x33 fits
        int r = blockIdx.x - BATCH;          // 0..1199
        int bx = r >> 3;                     // 0..149
        int jb = (r & 7) * 32;
        const float* cw; __half* Bt; int C, cb;
        if (bx < C0 / 64) { cw = cw0; Bt = B0w; C = C0; cb = bx * 64; }
        else              { cw = cw1; Bt = B1w; C = C1; cb = (bx - C0 / 64) * 64; }

        int tx = tid & 31, ty = tid >> 5;    // j, c-sub
        #pragma unroll
        for (int rr = 0; rr < 64; rr += 8) {
            int c = cb + ty + rr;
            int j = jb + tx;
            t[ty + rr][tx] = (j < NJ) ? cw[(size_t)c * NJ + j] : 0.f;
        }
        __syncthreads();
        int cx = tid & 63, jy = tid >> 6;    // c, j-sub
        #pragma unroll
        for (int rr = 0; rr < 32; rr += 4) {
            int j = jb + jy + rr;
            Bt[(size_t)j * C + cb + cx] = __float2half(t[cx][jy + rr]);
        }
    }
}

// ---------------- Layer 1 producer: full 32-k fold, column-owned --------------
// block = b (256 blocks). Thread g (< 200) owns column g; acc spans all 32 k.
__global__ void __launch_bounds__(256) prep1_kernel(
    const float* __restrict__ inp, const float* __restrict__ P0,
    const float* __restrict__ wq, const float* __restrict__ wk,
    const float* __restrict__ wv, __half* __restrict__ Xp)
{
    __shared__ float2 uw[KDIM][F0];   // (u*log2e, w), 10.2 KB
    const int b = blockIdx.x;         // 256
    const int tid = threadIdx.x;
    const float* P0b = P0 + (size_t)M0 * NJ;

    for (int i = tid; i < KDIM * F0; i += 256) {
        int f = i >> 5, k = i & 31;   // k minor: coalesced
        float x = inp[(size_t)(b * F0 + f) * KDIM + k];
        uw[k][f] = make_float2(x * wk[f * KDIM + k] * 1.44269504088896f,
                               x * wv[f * KDIM + k]);
    }
    __syncthreads();

    if (tid >= NJ) return;            // no further barriers: safe
    const int g = tid;

    float acc[F0];
    #pragma unroll
    for (int f = 0; f < F0; f++) acc[f] = 0.f;

    #pragma unroll
    for (int kg = 0; kg < 2; kg++) {
        float wqv[KG];
        {
            const float4* wp = reinterpret_cast<const float4*>(wq + g * KDIM + kg * KG);
            #pragma unroll
            for (int q = 0; q < KG / 4; q++) {
                float4 t = wp[q];
                wqv[q * 4 + 0] = t.x; wqv[q * 4 + 1] = t.y;
                wqv[q * 4 + 2] = t.z; wqv[q * 4 + 3] = t.w;
            }
        }
        float v[KG];
        #pragma unroll
        for (int kk = 0; kk < KG; kk++) {
            size_t idx = (size_t)(b * KDIM + kg * KG + kk) * NJ + g;
            v[kk] = P0[idx] + P0b[idx];
        }
        #pragma unroll
        for (int kk = 0; kk < KG; kk++) v[kk] *= wqv[kk];

        for (int kk = 0; kk < KG; kk++) {
            int k = kg * KG + kk;
            float vk = v[kk];
            float tw[F0];              // w * e
            float s0 = 0.f, s1 = 0.f, s2 = 0.f, s3 = 0.f;
            #pragma unroll
            for (int f = 0; f < F0; f += 4) {
                float2 p0 = uw[k][f + 0];
                float2 p1 = uw[k][f + 1];
                float2 p2 = uw[k][f + 2];
                float2 p3 = uw[k][f + 3];
                float e0 = ex2(p0.x * vk);
                float e1 = ex2(p1.x * vk);
                float e2 = ex2(p2.x * vk);
                float e3 = ex2(p3.x * vk);
                s0 += e0; s1 += e1; s2 += e2; s3 += e3;
                tw[f + 0] = p0.y * e0;
                tw[f + 1] = p1.y * e1;
                tw[f + 2] = p2.y * e2;
                tw[f + 3] = p3.y * e3;
            }
            float sinv = 1.0f / ((s0 + s1) + (s2 + s3));
            #pragma unroll
            for (int f = 0; f < F0; f++)
                acc[f] = fmaf(tw[f], sinv, acc[f]);
        }
    }

    __half* rowp = Xp + (size_t)b * C1;
    #pragma unroll
    for (int f = 0; f < F0; f++) {
        rowp[f * NJ + g] = __float2half(acc[f]);
    }
}

// ---------------- mma.sync fp16 GEMM body, compile-time NV specialization ----
template<int NV>
__device__ __forceinline__ void gemm_body(
    const __half* __restrict__ A,
    const __half* __restrict__ B,
    float* __restrict__ P, size_t sliceStride,
    int K, int cpz, int nc, char* sm)
{
    constexpr int n0 = (NV == 128) ? 0 : 128;
    constexpr int brows = (NV >= 128) ? 128 : ((NV + 15) & ~15);   // 128 or 80
    const int tid = threadIdx.x;
    const int lane = tid & 31;
    const int wid = tid >> 5;
    const int wm0 = (wid & 3) * 32;
    const int wn0 = (wid >> 2) * 64;
    const int m0 = blockIdx.x * 128;
    const int lda = K;
    const int c0 = blockIdx.z * cpz;
    int c1 = c0 + cpz; if (c1 > nc) c1 = nc;

    const uint32_t sb = smem_u32(sm);
    float* Pz = P + (size_t)blockIdx.z * sliceStride;

    float acc[2][8][4];
    #pragma unroll
    for (int i = 0; i < 2; i++)
        #pragma unroll
        for (int j = 0; j < 8; j++)
            #pragma unroll
            for (int l = 0; l < 4; l++) acc[i][j][l] = 0.f;

    auto gissue = [&](int c, int st) {
        int col = c * 64;
        uint32_t abase = sb + st * 32768;
        uint32_t bbase = abase + 16384;
        #pragma unroll
        for (int i = 0; i < 4; i++) {
            int idx = tid + 256 * i;
            int row = idx >> 3, q = idx & 7;
            cp16(abase + (row * 8 + (q ^ (row & 7))) * 16,
                 A + (size_t)(m0 + row) * lda + col + q * 8);
        }
        #pragma unroll
        for (int i = 0; i < 4; i++) {
            int idx = tid + 256 * i;
            int row = idx >> 3, q = idx & 7;
            if (row < brows)     // compile-time bound
                cp16(bbase + (row * 8 + (q ^ (row & 7))) * 16,
                     B + (size_t)(n0 + row) * lda + col + q * 8);
        }
        cp_commit();
    };

    if (c0 < c1) gissue(c0, 0); else cp_commit();
    if (c0 + 1 < c1) gissue(c0 + 1, 1); else cp_commit();

    const int t3 = lane >> 3;
    const int r8 = lane & 7;
    const bool fullwarp = (NV >= 128) || (wn0 == 0);

    for (int c = c0; c < c1; c++) {
        int rel = c - c0;
        int st = rel % 3;
        cp_wait1();
        __syncthreads();
        if (c + 2 < c1) gissue(c + 2, (rel + 2) % 3);
        uint32_t ab = sb + st * 32768;
        uint32_t bb = ab + 16384;
        #pragma unroll
        for (int ks = 0; ks < 4; ks++) {
            int kc = ks * 2;
            uint32_t afr[2][4], bfr[4][4];
            #pragma unroll
            for (int mt = 0; mt < 2; mt++) {
                int m = wm0 + mt * 16 + (t3 & 1) * 8 + r8;
                int q = kc + (t3 >> 1);
                ldm_x4(afr[mt], ab + (m * 8 + (q ^ (m & 7))) * 16);
            }
            if (fullwarp) {
                #pragma unroll
                for (int np = 0; np < 4; np++) {
                    int n = wn0 + np * 16 + (t3 >> 1) * 8 + r8;
                    int q = kc + (t3 & 1);
                    ldm_x4(bfr[np], bb + (n * 8 + (q ^ (n & 7))) * 16);
                }
                #pragma unroll
                for (int mt = 0; mt < 2; mt++)
                    #pragma unroll
                    for (int nt = 0; nt < 8; nt++)
                        mma_f16(acc[mt][nt], afr[mt],
                                bfr[nt >> 1][(nt & 1) * 2], bfr[nt >> 1][(nt & 1) * 2 + 1]);
            } else {
                int n = wn0 + (t3 >> 1) * 8 + r8;
                int q = kc + (t3 & 1);
                ldm_x4(bfr[0], bb + (n * 8 + (q ^ (n & 7))) * 16);
                #pragma unroll
                for (int mt = 0; mt < 2; mt++)
                    mma_f16(acc[mt][0], afr[mt], bfr[0][0], bfr[0][1]);
            }
        }
    }

    // epilogue: plain vectorized stores into this z-slice
    const int g = lane >> 2, t = lane & 3;
    #pragma unroll
    for (int mt = 0; mt < 2; mt++) {
        #pragma unroll
        for (int nt = 0; nt < 8; nt++) {
            int row = m0 + wm0 + mt * 16 + g;
            int col = n0 + wn0 + nt * 8 + t * 2;
            if (col < NJ) {
                *reinterpret_cast<float2*>(&Pz[(size_t)row * NJ + col]) =
                    make_float2(acc[mt][nt][0], acc[mt][nt][1]);
                *reinterpret_cast<float2*>(&Pz[(size_t)(row + 8) * NJ + col]) =
                    make_float2(acc[mt][nt][2], acc[mt][nt][3]);
            }
        }
    }
}

__global__ void __launch_bounds__(256, 2) mma_gemm_kernel(
    const __half* __restrict__ A,
    const __half* __restrict__ B,
    float* __restrict__ P, size_t sliceStride,
    int K, int cpz, int nc)
{
    extern __shared__ char sm[];       // 3 stages x (A 16KB + B 16KB) = 96KB
    if (blockIdx.y == 0)
        gemm_body<128>(A, B, P, sliceStride, K, cpz, nc, sm);
    else
        gemm_body<72>(A, B, P, sliceStride, K, cpz, nc, sm);
}

// ---------------- Final reduce: [B, 400], sums gemm0/gemm1 slices inline ------
__global__ void reduce_kernel(const float* __restrict__ P0,
                              const float* __restrict__ P1,
                              float* __restrict__ res)
{
    int i = blockIdx.x * 256 + threadIdx.x;
    if (i >= BATCH * 2 * NJ) return;
    int b = i / (2 * NJ), j = i % (2 * NJ);
    if (j < NJ) {
        const float* P0b = P0 + (size_t)M0 * NJ;
        float s = 0.f;
        #pragma unroll
        for (int k = 0; k < KDIM; k++) {
            size_t idx = (size_t)(b * KDIM + k) * NJ + j;
            s += P0[idx] + P0b[idx];
        }
        res[i] = s;
    } else {
        float s = 0.f;
        #pragma unroll
        for (int z = 0; z < Z1; z++)
            s += P1[(size_t)z * BATCH * NJ + (size_t)b * NJ + (j - NJ)];
        res[i] = s;
    }
}

extern "C" void kernel_launch(void* const* d_in, const int* in_sizes, int n_in,
                              void* d_out, int out_size)
{
    const float* inp = (const float*)d_in[0];
    const float* wq0 = (const float*)d_in[1];
    const float* wk0 = (const float*)d_in[2];
    const float* wv0 = (const float*)d_in[3];
    const float* cw0 = (const float*)d_in[4];
    const float* wq1 = (const float*)d_in[5];
    const float* wk1 = (const float*)d_in[6];
    const float* wv1 = (const float*)d_in[7];
    const float* cw1 = (const float*)d_in[8];
    float* out = (float*)d_out;

    __half *A0, *Xp, *B0, *B1;
    float *P0, *P1;
    cudaGetSymbolAddress((void**)&A0, g_A0);
    cudaGetSymbolAddress((void**)&Xp, g_Xp);
    cudaGetSymbolAddress((void**)&B0, g_B0);
    cudaGetSymbolAddress((void**)&B1, g_B1);
    cudaGetSymbolAddress((void**)&P0, g_P0);
    cudaGetSymbolAddress((void**)&P1, g_P1);

    cudaFuncSetAttribute(mma_gemm_kernel, cudaFuncAttributeMaxDynamicSharedMemorySize, 98304);

    // merged: prep0 (256 blocks) + both weight transposes (1200 blocks)
    prep0b_kernel<<<BATCH + (C0 / 64 + C1 / 64) * 8, 256>>>(
        inp, wq0, wk0, wv0, A0, cw0, cw1, B0, B1);

    // M=8192 (64 tiles), 2 n-tiles, nc=25 chunks (fp16), Z0=2 (cpz=13) -> 256 CTAs, 1 wave
    mma_gemm_kernel<<<dim3(64, 2, Z0), 256, 98304>>>(A0, B0, P0, (size_t)M0 * NJ, C0, 13, 25);

    // layer 1: full 32-k fold producer (256 blocks, 1 wave); sums P0 slices inline
    prep1_kernel<<<M1, 256>>>(inp, P0, wq1, wk1, wv1, Xp);
    // M=256 (2 tiles), nc=125 chunks (fp16), Z1=25 (cpz=5 exact) -> 100 CTAs
    mma_gemm_kernel<<<dim3(2, 2, Z1), 256, 98304>>>(Xp, B1, P1, (size_t)BATCH * NJ, C1, 5, 125);

    reduce_kernel<<<(BATCH * 2 * NJ + 255) / 256, 256>>>(P0, P1, out);
}